// round 13
// baseline (speedup 1.0000x reference)
#include <cuda_runtime.h>
#include <cuda_fp16.h>
#include <cstdint>
#include <cstddef>

// ============================================================================
// MotionGenerator fused: masked-conv1d(stride2,reflect7,K15)+pool+leakyReLU
// via mma.sync.m16n8k16 fp16 single-term (Ah*Bh), fp32 accum.
// R13 = R12 (warp-private B rings, no per-tap barriers) +
//   - TWO-TAP INTERLEAVED compute: per batch, two independent LDSM->MMA
//     streams so the tensor pipe stays fed through fragment-load latency.
//   - vectorized interior A-window loader (cuts alu/fma issue noise).
// ============================================================================

#define NG 12
#define NSLOT 85

__constant__ int   cOff[NG + 1] = {0, 8, 19, 26, 35, 39, 48, 52, 61, 65, 74, 78, 85};
__constant__ int   cE0[NG] = {0, 1, 3, 4, 6, 8, 10, 12, 14, 16, 18, 20};
__constant__ int   cE1[NG] = {-1, 2, -1, 5, 7, 9, 11, 13, 15, 17, 19, -1};

__constant__ int cSlotG[NSLOT] = {
    0,0,0,0,0,0,0,0,
    1,1,1,1,1,1,1,1,1,1,1,
    2,2,2,2,2,2,2,
    3,3,3,3,3,3,3,3,3,
    4,4,4,4,
    5,5,5,5,5,5,5,5,5,
    6,6,6,6,
    7,7,7,7,7,7,7,7,7,
    8,8,8,8,
    9,9,9,9,9,9,9,9,9,
    10,10,10,10,
    11,11,11,11,11,11,11
};

__constant__ int cJ[NSLOT] = {
    0,1,2,12,13,16,17,20,
    0,1,2,3,4,5,8,9,12,16,20,
    1,2,3,4,5,8,9,
    1,2,3,4,5,6,7,8,9,
    4,5,6,7,
    1,2,3,4,5,8,9,10,11,
    8,9,10,11,
    0,1,12,13,14,15,16,17,20,
    12,13,14,15,
    0,1,12,13,16,17,18,19,20,
    16,17,18,19,
    0,1,2,12,13,16,17
};

__constant__ float cC0[NSLOT] = {
    1,1,1,1,1,1,1,1,
    0.5f,0.5f,0.5f,0.5f,0.5f,0.0f,0.5f,0.0f,0.5f,0.5f,0.5f,
    1,1,1,1,1,1,1,
    0.5f,0.5f,0.5f,0.5f,0.5f,0.5f,0.0f,0.5f,0.5f,
    0.5f,0.5f,0.5f,0.5f,
    0.5f,0.5f,0.5f,0.5f,0.5f,0.5f,0.5f,0.5f,0.0f,
    0.5f,0.5f,0.5f,0.5f,
    0.5f,0.5f,0.5f,0.5f,0.5f,0.0f,0.5f,0.5f,0.5f,
    0.5f,0.5f,0.5f,0.5f,
    0.5f,0.5f,0.5f,0.5f,0.5f,0.5f,0.5f,0.0f,0.5f,
    0.5f,0.5f,0.5f,0.5f,
    1,1,1,1,1,1,1
};

__constant__ float cC1[NSLOT] = {
    0,0,0,0,0,0,0,0,
    0.5f,0.5f,0.5f,0.5f,0.5f,0.5f,0.5f,0.5f,0.0f,0.0f,0.5f,
    0,0,0,0,0,0,0,
    0.0f,0.5f,0.5f,0.5f,0.5f,0.5f,0.5f,0.5f,0.0f,
    0.0f,0.5f,0.5f,0.5f,
    0.0f,0.5f,0.5f,0.5f,0.0f,0.5f,0.5f,0.5f,0.5f,
    0.0f,0.5f,0.5f,0.5f,
    0.5f,0.0f,0.5f,0.5f,0.5f,0.5f,0.5f,0.0f,0.5f,
    0.0f,0.5f,0.5f,0.5f,
    0.5f,0.0f,0.5f,0.0f,0.5f,0.5f,0.5f,0.5f,0.5f,
    0.0f,0.5f,0.5f,0.5f,
    0,0,0,0,0,0,0
};

// Folded weights, fp16, dense [s][k][oc=128][ci=64]
__device__ __align__(16) __half g_Wh[(size_t)NSLOT * 15 * 8192];

// ---------------------------------------------------------------------------
// smem (bytes):
//   [0,512)        pooled bias (128 f32)
//   [512,+39168)   A: [parity(2)][q=136][72 halves], pitch 144B (shared)
//   [39680,+73728) B: 8 warps x 2 bufs x 4608B (32 oc rows x 144B, private)
// Epilogue reuses [512,...) as D staging [128][132 f32] (67584B).
// ---------------------------------------------------------------------------
#define AP    72
#define AROWS 136
#define ASZ   (AROWS * AP)             // 9792 halves per parity
#define A_OFF 512
#define B_OFF (A_OFF + 2 * ASZ * 2)    // 39680
#define BSLICE 4608                    // 32 rows * 144 B
#define SMEM_BYTES (B_OFF + 8 * 2 * BSLICE)   // 113408

__device__ __forceinline__ uint32_t smem_u32(const void* p) {
    uint32_t a;
    asm("{ .reg .u64 t; cvta.to.shared.u64 t, %1; cvt.u32.u64 %0, t; }" : "=r"(a) : "l"(p));
    return a;
}

__device__ __forceinline__ void mma16816(float* d, const uint32_t* a,
                                         uint32_t b0, uint32_t b1) {
    asm volatile(
        "mma.sync.aligned.m16n8k16.row.col.f32.f16.f16.f32 "
        "{%0,%1,%2,%3}, {%4,%5,%6,%7}, {%8,%9}, {%0,%1,%2,%3};"
        : "+f"(d[0]), "+f"(d[1]), "+f"(d[2]), "+f"(d[3])
        : "r"(a[0]), "r"(a[1]), "r"(a[2]), "r"(a[3]), "r"(b0), "r"(b1));
}

__device__ __forceinline__ void ldmx4(uint32_t* r, uint32_t addr) {
    asm volatile("ldmatrix.sync.aligned.m8n8.x4.shared.b16 {%0,%1,%2,%3}, [%4];"
                 : "=r"(r[0]), "=r"(r[1]), "=r"(r[2]), "=r"(r[3]) : "r"(addr));
}

// pack two fp32 -> half2: low half = lo, high half = hi
__device__ __forceinline__ uint32_t pkh2(float hi, float lo) {
    uint32_t d;
    asm("cvt.rn.f16x2.f32 %0, %1, %2;" : "=r"(d) : "f"(hi), "f"(lo));
    return d;
}

// ---------------------------------------------------------------------------
__global__ void prep_wc(const float* __restrict__ weight) {
    const int s  = blockIdx.x;
    const int oc = blockIdx.y;
    const int g  = cSlotG[s];
    const int j  = cJ[s];
    const float c0 = cC0[s], c1 = cC1[s];
    const int e0 = cE0[g], e1 = cE1[g];

    const float* __restrict__ w0 = weight + (size_t)(e0 * 128 + oc) * 20160 + (size_t)j * 960;
    const float* __restrict__ w1 = (e1 >= 0)
        ? weight + (size_t)(e1 * 128 + oc) * 20160 + (size_t)j * 960 : nullptr;

    for (int q = threadIdx.x; q < 960; q += blockDim.x) {
        float v = c0 * w0[q];
        if (w1) v += c1 * w1[q];
        const int ci = q / 15;
        const int k  = q - ci * 15;
        g_Wh[((size_t)(s * 15 + k) * 128 + oc) * 64 + ci] = __float2half_rn(v);
    }
}

// ---------------------------------------------------------------------------
// Main: 256 threads, 8 warps (2 t-groups x 4 oc-slices), warp tile 64t x 32oc.
// ---------------------------------------------------------------------------
__global__ __launch_bounds__(256, 2)
void motion_hmma(const float* __restrict__ x,
                 const float* __restrict__ bias,
                 float* __restrict__ out) {
    extern __shared__ __align__(16) char smem[];
    float* sbias = reinterpret_cast<float*>(smem);
    __half* Aarr = reinterpret_cast<__half*>(smem + A_OFF);
    const uint32_t Asm = smem_u32(Aarr);
    const uint32_t Bsm = smem_u32(smem + B_OFF);

    const int tid  = threadIdx.x;
    const int w    = tid >> 5;       // 0..7
    const int lane = tid & 31;

    const int tile = blockIdx.x;   // 0..15
    const int b    = blockIdx.y;   // 0..7
    const int g    = blockIdx.z;   // 0..11
    const int t0   = tile << 7;
    const int base = 2 * t0 - 7;
    const bool interior = (tile >= 1) && (tile <= 14);

    const int warp_tm = (w & 1) * 64;    // t offset (64 rows)
    const int warp_on = (w >> 1) * 32;   // oc offset (32 cols, warp-private)
    const uint32_t Bwarp = Bsm + (uint32_t)w * (2 * BSLICE);

    if (tid < 128) {
        const int e0 = cE0[g], e1 = cE1[g];
        float bv = bias[e0 * 128 + tid];
        if (e1 >= 0) bv = 0.5f * (bv + bias[e1 * 128 + tid]);
        sbias[tid] = bv;
    }

    float acc[4][4][4];
#pragma unroll
    for (int mi = 0; mi < 4; ++mi)
#pragma unroll
        for (int ni = 0; ni < 4; ++ni)
#pragma unroll
            for (int q = 0; q < 4; ++q) acc[mi][ni][q] = 0.f;

    const int off0 = cOff[g];
    const int nj   = cOff[g + 1] - off0;
    const int nt   = nj * 15;

    // warp-private cp.async: this warp's 32-oc slice of tap n -> buf n&1
    auto issue = [&](int n) {
        const int s = off0 + n / 15;
        const int k = n - (n / 15) * 15;
        const __half* __restrict__ tb =
            g_Wh + (size_t)(s * 15 + k) * 8192 + (size_t)warp_on * 64;
        const uint32_t dbase = Bwarp + (uint32_t)(n & 1) * BSLICE;
#pragma unroll
        for (int i = 0; i < 8; ++i) {
            const int c   = lane + (i << 5);      // 0..255
            const int row = c >> 3;               // 0..31 (local oc)
            const int col = c & 7;                // 16B chunk
            const __half* src = tb + (size_t)row * 64 + col * 8;
            const uint32_t dst = dbase + row * 144 + col * 16;
            asm volatile("cp.async.cg.shared.global [%0], [%1], 16;"
                         :: "r"(dst), "l"(src) : "memory");
        }
        asm volatile("cp.async.commit_group;" ::: "memory");
    };

    issue(0);
    if (nt > 1) issue(1);

    // per-lane ldmatrix address components
    const uint32_t aoff = (uint32_t)(lane & 15) * 144 + ((lane >> 4) ? 16u : 0u);
    const uint32_t boff = (uint32_t)(((lane >> 4) & 1) * 8 + (lane & 7)) * 144
                        + (((lane >> 3) & 1) ? 16u : 0u);   // local rows 0..15

    // single-tap compute (R12 body) — used for the odd 15th tap
    auto comp1 = [&](int k, int n) {
        const uint32_t Ap = Asm + (uint32_t)(k & 1) * (ASZ * 2)
                          + (uint32_t)(warp_tm + (k >> 1)) * 144 + aoff;
        const uint32_t Bp = Bwarp + (uint32_t)(n & 1) * BSLICE + boff;
#pragma unroll
        for (int cc = 0; cc < 4; ++cc) {
            uint32_t a[4][4];
#pragma unroll
            for (int mi = 0; mi < 4; ++mi)
                ldmx4(a[mi], Ap + cc * 32 + mi * (16 * 144));
#pragma unroll
            for (int p = 0; p < 2; ++p) {
                uint32_t bb[4];
                ldmx4(bb, Bp + cc * 32 + p * (16 * 144));
#pragma unroll
                for (int mi = 0; mi < 4; ++mi) {
                    mma16816(acc[mi][2 * p],     a[mi], bb[0], bb[1]);
                    mma16816(acc[mi][2 * p + 1], a[mi], bb[2], bb[3]);
                }
            }
        }
    };

    // TWO-TAP interleaved compute: taps k and k+1 are independent streams
    // (different parity array, different private B buffer).
    auto comp2 = [&](int k, int n) {
        const uint32_t Ap0 = Asm + (uint32_t)(k & 1) * (ASZ * 2)
                           + (uint32_t)(warp_tm + (k >> 1)) * 144 + aoff;
        const uint32_t Ap1 = Asm + (uint32_t)((k + 1) & 1) * (ASZ * 2)
                           + (uint32_t)(warp_tm + ((k + 1) >> 1)) * 144 + aoff;
        const uint32_t Bp0 = Bwarp + (uint32_t)(n & 1) * BSLICE + boff;
        const uint32_t Bp1 = Bwarp + (uint32_t)((n + 1) & 1) * BSLICE + boff;
#pragma unroll
        for (int cc = 0; cc < 4; ++cc) {
            uint32_t a0[4][4], a1[4][4];
#pragma unroll
            for (int mi = 0; mi < 4; ++mi)
                ldmx4(a0[mi], Ap0 + cc * 32 + mi * (16 * 144));
#pragma unroll
            for (int mi = 0; mi < 4; ++mi)
                ldmx4(a1[mi], Ap1 + cc * 32 + mi * (16 * 144));
            uint32_t b0[2][4], b1[2][4];
#pragma unroll
            for (int p = 0; p < 2; ++p) {
                ldmx4(b0[p], Bp0 + cc * 32 + p * (16 * 144));
                ldmx4(b1[p], Bp1 + cc * 32 + p * (16 * 144));
            }
            // two independent MMA streams; scheduler interleaves freely
#pragma unroll
            for (int p = 0; p < 2; ++p) {
#pragma unroll
                for (int mi = 0; mi < 4; ++mi) {
                    mma16816(acc[mi][2 * p],     a0[mi], b0[p][0], b0[p][1]);
                    mma16816(acc[mi][2 * p + 1], a0[mi], b0[p][2], b0[p][3]);
                    mma16816(acc[mi][2 * p],     a1[mi], b1[p][0], b1[p][1]);
                    mma16816(acc[mi][2 * p + 1], a1[mi], b1[p][2], b1[p][3]);
                }
            }
        }
    };

    for (int jj = 0; jj < nj; ++jj) {
        const int j = cJ[off0 + jj];

        __syncthreads();   // all warps done reading previous joint's A window

        // ---- window load: x -> A[parity][q][ci] fp16 (shared) ----
        const float* __restrict__ xj = x + ((size_t)b * 1344 + (size_t)j * 64) * 4096;
        if (interior) {
            // vector path: positions [2t0-8, 2t0+263], no reflection
            const float* __restrict__ r0p = xj + (size_t)(2 * lane) * 4096 + (2 * t0 - 8);
            const float* __restrict__ r1p = r0p + 4096;
            uint32_t* __restrict__ Ae32 =
                reinterpret_cast<uint32_t*>(Aarr) + lane;              // row stride 36 u32
            uint32_t* __restrict__ Ao32 = Ae32 + (ASZ >> 1);
#pragma unroll
            for (int i = 0; i < 9; ++i) {
                const int c = w + 8 * i;
                if (c >= 68) break;
                const float4 fa = *reinterpret_cast<const float4*>(r0p + 4 * c);
                const float4 fb = *reinterpret_cast<const float4*>(r1p + 4 * c);
                if (c > 0) Ao32[(size_t)(2 * c - 1) * 36] = pkh2(fb.x, fa.x);  // r=4c-1
                Ae32[(size_t)(2 * c    ) * 36] = pkh2(fb.y, fa.y);             // r=4c
                Ao32[(size_t)(2 * c    ) * 36] = pkh2(fb.z, fa.z);             // r=4c+1
                Ae32[(size_t)(2 * c + 1) * 36] = pkh2(fb.w, fa.w);             // r=4c+2
            }
        } else {
            for (int ci = w; ci < 64; ci += 8) {
                const float* __restrict__ src = xj + (size_t)ci * 4096;
                for (int r = lane; r < 269; r += 32) {
                    int pos = base + r;
                    pos = pos < 0 ? -pos : pos;
                    pos = pos > 4095 ? 8190 - pos : pos;
                    Aarr[(size_t)(r & 1) * ASZ + (r >> 1) * AP + ci] =
                        __float2half_rn(src[pos]);
                }
            }
        }
        __syncthreads();   // A visible to all warps

        // ---- taps in batches of 2, NO CTA barriers (warp-private B rings) ----
        for (int kb = 0; kb < 15; kb += 2) {
            const int n = jj * 15 + kb;
            if (kb == 14) {
                // single tail tap
                if (n + 1 < nt) {
                    asm volatile("cp.async.wait_group 1;" ::: "memory");
                } else {
                    asm volatile("cp.async.wait_group 0;" ::: "memory");
                }
                comp1(kb, n);
                if (n + 2 < nt) issue(n + 2);
            } else {
                // both groups n, n+1 must be resident (they use both buffers)
                asm volatile("cp.async.wait_group 0;" ::: "memory");
                comp2(kb, n);
                // refill both buffers AFTER all LDSMs of this batch
                if (n + 2 < nt) issue(n + 2);
                if (n + 3 < nt) issue(n + 3);
            }
        }
    }

    __syncthreads();   // all MMAs done before staging overwrites A/B regions

    // ---- epilogue: transpose D via smem, bias + leaky relu ----
    float* Ds = reinterpret_cast<float*>(smem + A_OFF);   // [oc=128][pitch 132]
    {
        const int grow = lane >> 2;
        const int colb = (lane & 3) * 2;
#pragma unroll
        for (int mi = 0; mi < 4; ++mi) {
            const int row = warp_tm + mi * 16 + grow;
#pragma unroll
            for (int ni = 0; ni < 4; ++ni) {
                const int col = warp_on + ni * 8 + colb;
                Ds[(col    ) * 132 + row    ] = acc[mi][ni][0];
                Ds[(col + 1) * 132 + row    ] = acc[mi][ni][1];
                Ds[(col    ) * 132 + row + 8] = acc[mi][ni][2];
                Ds[(col + 1) * 132 + row + 8] = acc[mi][ni][3];
            }
        }
    }
    __syncthreads();

    {
        const int oc = tid >> 1, half = tid & 1;
        const float bv = sbias[oc];
        const float4* __restrict__ sp =
            reinterpret_cast<const float4*>(Ds + oc * 132 + half * 64);
        float4* __restrict__ op = reinterpret_cast<float4*>(
            out + ((size_t)b * 1536 + (size_t)g * 128 + oc) * 2048 + t0 + half * 64);
#pragma unroll
        for (int i = 0; i < 16; ++i) {
            float4 v = sp[i];
            v.x += bv; v.y += bv; v.z += bv; v.w += bv;
            v.x = v.x > 0.f ? v.x : 0.2f * v.x;
            v.y = v.y > 0.f ? v.y : 0.2f * v.y;
            v.z = v.z > 0.f ? v.z : 0.2f * v.z;
            v.w = v.w > 0.f ? v.w : 0.2f * v.w;
            op[i] = v;
        }
    }
}

// ---------------------------------------------------------------------------
extern "C" void kernel_launch(void* const* d_in, const int* in_sizes, int n_in,
                              void* d_out, int out_size) {
    (void)in_sizes; (void)n_in; (void)out_size;
    const float* x      = (const float*)d_in[0];   // [8][1344][4096]
    const float* weight = (const float*)d_in[1];   // [2688][1344][15]
    const float* bias   = (const float*)d_in[2];   // [2688]
    float* out          = (float*)d_out;           // [8][1536][2048]

    cudaFuncSetAttribute(motion_hmma, cudaFuncAttributeMaxDynamicSharedMemorySize,
                         SMEM_BYTES);

    dim3 gp(NSLOT, 128);
    prep_wc<<<gp, 256>>>(weight);

    dim3 gm(16, 8, NG);
    motion_hmma<<<gm, 256, SMEM_BYTES>>>(x, bias, out);
}

// round 14
// speedup vs baseline: 1.1257x; 1.1257x over previous
#include <cuda_runtime.h>
#include <cuda_fp16.h>
#include <cstdint>
#include <cstddef>

// ============================================================================
// MotionGenerator fused: masked-conv1d(stride2,reflect7,K15)+pool+leakyReLU
// via mma.sync.m16n8k16 fp16 single-term (Ah*Bh), fp32 accum.
// R14 = R12 champion (warp-private B rings, no per-tap barriers)
//       + vectorized interior A-window loader (only change).
// ============================================================================

#define NG 12
#define NSLOT 85

__constant__ int   cOff[NG + 1] = {0, 8, 19, 26, 35, 39, 48, 52, 61, 65, 74, 78, 85};
__constant__ int   cE0[NG] = {0, 1, 3, 4, 6, 8, 10, 12, 14, 16, 18, 20};
__constant__ int   cE1[NG] = {-1, 2, -1, 5, 7, 9, 11, 13, 15, 17, 19, -1};

__constant__ int cSlotG[NSLOT] = {
    0,0,0,0,0,0,0,0,
    1,1,1,1,1,1,1,1,1,1,1,
    2,2,2,2,2,2,2,
    3,3,3,3,3,3,3,3,3,
    4,4,4,4,
    5,5,5,5,5,5,5,5,5,
    6,6,6,6,
    7,7,7,7,7,7,7,7,7,
    8,8,8,8,
    9,9,9,9,9,9,9,9,9,
    10,10,10,10,
    11,11,11,11,11,11,11
};

__constant__ int cJ[NSLOT] = {
    0,1,2,12,13,16,17,20,
    0,1,2,3,4,5,8,9,12,16,20,
    1,2,3,4,5,8,9,
    1,2,3,4,5,6,7,8,9,
    4,5,6,7,
    1,2,3,4,5,8,9,10,11,
    8,9,10,11,
    0,1,12,13,14,15,16,17,20,
    12,13,14,15,
    0,1,12,13,16,17,18,19,20,
    16,17,18,19,
    0,1,2,12,13,16,17
};

__constant__ float cC0[NSLOT] = {
    1,1,1,1,1,1,1,1,
    0.5f,0.5f,0.5f,0.5f,0.5f,0.0f,0.5f,0.0f,0.5f,0.5f,0.5f,
    1,1,1,1,1,1,1,
    0.5f,0.5f,0.5f,0.5f,0.5f,0.5f,0.0f,0.5f,0.5f,
    0.5f,0.5f,0.5f,0.5f,
    0.5f,0.5f,0.5f,0.5f,0.5f,0.5f,0.5f,0.5f,0.0f,
    0.5f,0.5f,0.5f,0.5f,
    0.5f,0.5f,0.5f,0.5f,0.5f,0.0f,0.5f,0.5f,0.5f,
    0.5f,0.5f,0.5f,0.5f,
    0.5f,0.5f,0.5f,0.5f,0.5f,0.5f,0.5f,0.0f,0.5f,
    0.5f,0.5f,0.5f,0.5f,
    1,1,1,1,1,1,1
};

__constant__ float cC1[NSLOT] = {
    0,0,0,0,0,0,0,0,
    0.5f,0.5f,0.5f,0.5f,0.5f,0.5f,0.5f,0.5f,0.0f,0.0f,0.5f,
    0,0,0,0,0,0,0,
    0.0f,0.5f,0.5f,0.5f,0.5f,0.5f,0.5f,0.5f,0.0f,
    0.0f,0.5f,0.5f,0.5f,
    0.0f,0.5f,0.5f,0.5f,0.0f,0.5f,0.5f,0.5f,0.5f,
    0.0f,0.5f,0.5f,0.5f,
    0.5f,0.0f,0.5f,0.5f,0.5f,0.5f,0.5f,0.0f,0.5f,
    0.0f,0.5f,0.5f,0.5f,
    0.5f,0.0f,0.5f,0.0f,0.5f,0.5f,0.5f,0.5f,0.5f,
    0.0f,0.5f,0.5f,0.5f,
    0,0,0,0,0,0,0
};

// Folded weights, fp16, dense [s][k][oc=128][ci=64]
__device__ __align__(16) __half g_Wh[(size_t)NSLOT * 15 * 8192];

// ---------------------------------------------------------------------------
// smem (bytes):
//   [0,512)        pooled bias (128 f32)
//   [512,+39168)   A: [parity(2)][q=136][72 halves], pitch 144B (shared)
//   [39680,+73728) B: 8 warps x 2 bufs x 4608B (32 oc rows x 144B, private)
// Epilogue reuses [512,...) as D staging [128][132 f32] (67584B).
// ---------------------------------------------------------------------------
#define AP    72
#define AROWS 136
#define ASZ   (AROWS * AP)             // 9792 halves per parity
#define A_OFF 512
#define B_OFF (A_OFF + 2 * ASZ * 2)    // 39680
#define BSLICE 4608                    // 32 rows * 144 B
#define SMEM_BYTES (B_OFF + 8 * 2 * BSLICE)   // 113408

__device__ __forceinline__ uint32_t smem_u32(const void* p) {
    uint32_t a;
    asm("{ .reg .u64 t; cvta.to.shared.u64 t, %1; cvt.u32.u64 %0, t; }" : "=r"(a) : "l"(p));
    return a;
}

__device__ __forceinline__ void mma16816(float* d, const uint32_t* a,
                                         uint32_t b0, uint32_t b1) {
    asm volatile(
        "mma.sync.aligned.m16n8k16.row.col.f32.f16.f16.f32 "
        "{%0,%1,%2,%3}, {%4,%5,%6,%7}, {%8,%9}, {%0,%1,%2,%3};"
        : "+f"(d[0]), "+f"(d[1]), "+f"(d[2]), "+f"(d[3])
        : "r"(a[0]), "r"(a[1]), "r"(a[2]), "r"(a[3]), "r"(b0), "r"(b1));
}

__device__ __forceinline__ void ldmx4(uint32_t* r, uint32_t addr) {
    asm volatile("ldmatrix.sync.aligned.m8n8.x4.shared.b16 {%0,%1,%2,%3}, [%4];"
                 : "=r"(r[0]), "=r"(r[1]), "=r"(r[2]), "=r"(r[3]) : "r"(addr));
}

// pack two fp32 -> half2: low half = lo, high half = hi
__device__ __forceinline__ uint32_t pkh2(float hi, float lo) {
    uint32_t d;
    asm("cvt.rn.f16x2.f32 %0, %1, %2;" : "=r"(d) : "f"(hi), "f"(lo));
    return d;
}

// ---------------------------------------------------------------------------
__global__ void prep_wc(const float* __restrict__ weight) {
    const int s  = blockIdx.x;
    const int oc = blockIdx.y;
    const int g  = cSlotG[s];
    const int j  = cJ[s];
    const float c0 = cC0[s], c1 = cC1[s];
    const int e0 = cE0[g], e1 = cE1[g];

    const float* __restrict__ w0 = weight + (size_t)(e0 * 128 + oc) * 20160 + (size_t)j * 960;
    const float* __restrict__ w1 = (e1 >= 0)
        ? weight + (size_t)(e1 * 128 + oc) * 20160 + (size_t)j * 960 : nullptr;

    for (int q = threadIdx.x; q < 960; q += blockDim.x) {
        float v = c0 * w0[q];
        if (w1) v += c1 * w1[q];
        const int ci = q / 15;
        const int k  = q - ci * 15;
        g_Wh[((size_t)(s * 15 + k) * 128 + oc) * 64 + ci] = __float2half_rn(v);
    }
}

// ---------------------------------------------------------------------------
// Main: 256 threads, 8 warps (2 t-groups x 4 oc-slices), warp tile 64t x 32oc.
// ---------------------------------------------------------------------------
__global__ __launch_bounds__(256, 2)
void motion_hmma(const float* __restrict__ x,
                 const float* __restrict__ bias,
                 float* __restrict__ out) {
    extern __shared__ __align__(16) char smem[];
    float* sbias = reinterpret_cast<float*>(smem);
    __half* Aarr = reinterpret_cast<__half*>(smem + A_OFF);
    const uint32_t Asm = smem_u32(Aarr);
    const uint32_t Bsm = smem_u32(smem + B_OFF);

    const int tid  = threadIdx.x;
    const int w    = tid >> 5;       // 0..7
    const int lane = tid & 31;

    const int tile = blockIdx.x;   // 0..15
    const int b    = blockIdx.y;   // 0..7
    const int g    = blockIdx.z;   // 0..11
    const int t0   = tile << 7;
    const int base = 2 * t0 - 7;
    const bool interior = (tile >= 1) && (tile <= 14);

    const int warp_tm = (w & 1) * 64;    // t offset (64 rows)
    const int warp_on = (w >> 1) * 32;   // oc offset (32 cols, warp-private)
    const uint32_t Bwarp = Bsm + (uint32_t)w * (2 * BSLICE);

    if (tid < 128) {
        const int e0 = cE0[g], e1 = cE1[g];
        float bv = bias[e0 * 128 + tid];
        if (e1 >= 0) bv = 0.5f * (bv + bias[e1 * 128 + tid]);
        sbias[tid] = bv;
    }

    float acc[4][4][4];
#pragma unroll
    for (int mi = 0; mi < 4; ++mi)
#pragma unroll
        for (int ni = 0; ni < 4; ++ni)
#pragma unroll
            for (int q = 0; q < 4; ++q) acc[mi][ni][q] = 0.f;

    const int off0 = cOff[g];
    const int nj   = cOff[g + 1] - off0;
    const int nt   = nj * 15;

    // warp-private cp.async: this warp's 32-oc slice of tap n -> buf n&1
    auto issue = [&](int n) {
        const int s = off0 + n / 15;
        const int k = n - (n / 15) * 15;
        const __half* __restrict__ tb =
            g_Wh + (size_t)(s * 15 + k) * 8192 + (size_t)warp_on * 64;
        const uint32_t dbase = Bwarp + (uint32_t)(n & 1) * BSLICE;
#pragma unroll
        for (int i = 0; i < 8; ++i) {
            const int c   = lane + (i << 5);      // 0..255
            const int row = c >> 3;               // 0..31 (local oc)
            const int col = c & 7;                // 16B chunk
            const __half* src = tb + (size_t)row * 64 + col * 8;
            const uint32_t dst = dbase + row * 144 + col * 16;
            asm volatile("cp.async.cg.shared.global [%0], [%1], 16;"
                         :: "r"(dst), "l"(src) : "memory");
        }
        asm volatile("cp.async.commit_group;" ::: "memory");
    };

    issue(0);
    if (nt > 1) issue(1);

    // per-lane ldmatrix address components
    const uint32_t aoff = (uint32_t)(lane & 15) * 144 + ((lane >> 4) ? 16u : 0u);
    const uint32_t boff = (uint32_t)(((lane >> 4) & 1) * 8 + (lane & 7)) * 144
                        + (((lane >> 3) & 1) ? 16u : 0u);   // local rows 0..15

    for (int jj = 0; jj < nj; ++jj) {
        const int j = cJ[off0 + jj];

        __syncthreads();   // all warps done reading previous joint's A window

        // ---- window load: x -> A[parity][q][ci] fp16 (shared) ----
        const float* __restrict__ xj = x + ((size_t)b * 1344 + (size_t)j * 64) * 4096;
        if (interior) {
            // vector path: positions [2t0-8, 2t0+263], no reflection.
            // lane -> ci pair (2*lane, 2*lane+1); warps stride 4-position chunks.
            const float* __restrict__ r0p = xj + (size_t)(2 * lane) * 4096 + (2 * t0 - 8);
            const float* __restrict__ r1p = r0p + 4096;
            uint32_t* __restrict__ Ae32 =
                reinterpret_cast<uint32_t*>(Aarr) + lane;              // row stride 36 u32
            uint32_t* __restrict__ Ao32 = Ae32 + (ASZ >> 1);
#pragma unroll
            for (int i = 0; i < 9; ++i) {
                const int c = w + 8 * i;
                if (c >= 68) break;
                const float4 fa = *reinterpret_cast<const float4*>(r0p + 4 * c);
                const float4 fb = *reinterpret_cast<const float4*>(r1p + 4 * c);
                if (c > 0) Ao32[(size_t)(2 * c - 1) * 36] = pkh2(fb.x, fa.x);  // r=4c-1
                Ae32[(size_t)(2 * c    ) * 36] = pkh2(fb.y, fa.y);             // r=4c
                Ao32[(size_t)(2 * c    ) * 36] = pkh2(fb.z, fa.z);             // r=4c+1
                Ae32[(size_t)(2 * c + 1) * 36] = pkh2(fb.w, fa.w);             // r=4c+2
            }
        } else {
            // boundary path: scalar with reflection
            for (int ci = w; ci < 64; ci += 8) {
                const float* __restrict__ src = xj + (size_t)ci * 4096;
                for (int r = lane; r < 269; r += 32) {
                    int pos = base + r;
                    pos = pos < 0 ? -pos : pos;
                    pos = pos > 4095 ? 8190 - pos : pos;
                    Aarr[(size_t)(r & 1) * ASZ + (r >> 1) * AP + ci] =
                        __float2half_rn(src[pos]);
                }
            }
        }
        __syncthreads();   // A visible to all warps

        // ---- 15 taps, NO CTA barriers: each warp free-runs its own B ring ----
        for (int k = 0; k < 15; ++k) {
            const int n = jj * 15 + k;

            if (n + 1 < nt) {
                asm volatile("cp.async.wait_group 1;" ::: "memory");   // group n done
            } else {
                asm volatile("cp.async.wait_group 0;" ::: "memory");
            }

            const uint32_t Ap = Asm + (uint32_t)(k & 1) * (ASZ * 2)
                              + (uint32_t)(warp_tm + (k >> 1)) * 144 + aoff;
            const uint32_t Bp = Bwarp + (uint32_t)(n & 1) * BSLICE + boff;

#pragma unroll
            for (int cc = 0; cc < 4; ++cc) {
                uint32_t a[4][4];
#pragma unroll
                for (int mi = 0; mi < 4; ++mi)
                    ldmx4(a[mi], Ap + cc * 32 + mi * (16 * 144));
#pragma unroll
                for (int p = 0; p < 2; ++p) {
                    uint32_t bb[4];
                    ldmx4(bb, Bp + cc * 32 + p * (16 * 144));
#pragma unroll
                    for (int mi = 0; mi < 4; ++mi) {
                        mma16816(acc[mi][2 * p],     a[mi], bb[0], bb[1]);
                        mma16816(acc[mi][2 * p + 1], a[mi], bb[2], bb[3]);
                    }
                }
            }

            // refill the ring AFTER this tap's LDSMs (warp-private WAR-safe)
            if (n + 2 < nt) issue(n + 2);
        }
    }

    __syncthreads();   // all MMAs done before staging overwrites A/B regions

    // ---- epilogue: transpose D via smem, bias + leaky relu ----
    float* Ds = reinterpret_cast<float*>(smem + A_OFF);   // [oc=128][pitch 132]
    {
        const int grow = lane >> 2;
        const int colb = (lane & 3) * 2;
#pragma unroll
        for (int mi = 0; mi < 4; ++mi) {
            const int row = warp_tm + mi * 16 + grow;
#pragma unroll
            for (int ni = 0; ni < 4; ++ni) {
                const int col = warp_on + ni * 8 + colb;
                Ds[(col    ) * 132 + row    ] = acc[mi][ni][0];
                Ds[(col + 1) * 132 + row    ] = acc[mi][ni][1];
                Ds[(col    ) * 132 + row + 8] = acc[mi][ni][2];
                Ds[(col + 1) * 132 + row + 8] = acc[mi][ni][3];
            }
        }
    }
    __syncthreads();

    {
        const int oc = tid >> 1, half = tid & 1;
        const float bv = sbias[oc];
        const float4* __restrict__ sp =
            reinterpret_cast<const float4*>(Ds + oc * 132 + half * 64);
        float4* __restrict__ op = reinterpret_cast<float4*>(
            out + ((size_t)b * 1536 + (size_t)g * 128 + oc) * 2048 + t0 + half * 64);
#pragma unroll
        for (int i = 0; i < 16; ++i) {
            float4 v = sp[i];
            v.x += bv; v.y += bv; v.z += bv; v.w += bv;
            v.x = v.x > 0.f ? v.x : 0.2f * v.x;
            v.y = v.y > 0.f ? v.y : 0.2f * v.y;
            v.z = v.z > 0.f ? v.z : 0.2f * v.z;
            v.w = v.w > 0.f ? v.w : 0.2f * v.w;
            op[i] = v;
        }
    }
}

// ---------------------------------------------------------------------------
extern "C" void kernel_launch(void* const* d_in, const int* in_sizes, int n_in,
                              void* d_out, int out_size) {
    (void)in_sizes; (void)n_in; (void)out_size;
    const float* x      = (const float*)d_in[0];   // [8][1344][4096]
    const float* weight = (const float*)d_in[1];   // [2688][1344][15]
    const float* bias   = (const float*)d_in[2];   // [2688]
    float* out          = (float*)d_out;           // [8][1536][2048]

    cudaFuncSetAttribute(motion_hmma, cudaFuncAttributeMaxDynamicSharedMemorySize,
                         SMEM_BYTES);

    dim3 gp(NSLOT, 128);
    prep_wc<<<gp, 256>>>(weight);

    dim3 gm(16, 8, NG);
    motion_hmma<<<gm, 256, SMEM_BYTES>>>(x, bias, out);
}